// round 1
// baseline (speedup 1.0000x reference)
#include <cuda_runtime.h>

#define Nn 150000
#define Ee 4800000
#define NOUT 68
#define CAP 65536

// ---------------- device scratch (no allocation allowed) ----------------
__device__ float g0v[Nn * 8];     // augmented input features (8 real dims; const col implicit)
__device__ float S1v[Nn * 8];     // layer-1 aggregation sums -> normalized to g1 in place
__device__ float S2v[Nn * 8];     // layer-2 aggregation sums -> normalized to g2 in place
__device__ float d2v[Nn];         // g2 const-column: M(M(1))
__device__ int   cntv[Nn];        // in-degree
__device__ int   zcv[Nn];         // # in-neighbors with degree 0 (exactness correction)
__device__ int   any_zero;        // flag: does any degree-0 node exist?
__device__ int   c_src[CAP];      // compacted edges with dst < NOUT
__device__ int   c_dst[CAP];
__device__ int   c_count;
__device__ float out_acc[NOUT * 9]; // Sigma over compacted edges of [g2, d2]
__device__ float Cmat[4 * 9 * 3];   // C_k[9][3], k = power of M

// ---------------- helpers ----------------
__device__ __forceinline__ void red_v4(float* addr, float4 v) {
    asm volatile("red.global.add.v4.f32 [%0], {%1,%2,%3,%4};"
                 :: "l"(addr), "f"(v.x), "f"(v.y), "f"(v.z), "f"(v.w)
                 : "memory");
}

// ---------------- K0: build the 4 collapsed 9x3 weight matrices ----------------
// h~_L = sum_k M^k(h~_0) T_k, recurrence T'_k = T_k*Wr^ + T_{k-1}*Wl^
__global__ void build_cmat(const float* __restrict__ Wl1, const float* __restrict__ Wr1,
                           const float* __restrict__ b1,
                           const float* __restrict__ Wl2, const float* __restrict__ Wr2,
                           const float* __restrict__ b2,
                           const float* __restrict__ Wl3, const float* __restrict__ Wr3,
                           const float* __restrict__ b3) {
    __shared__ float T0[9 * 17], T1[9 * 17];
    __shared__ float U0[9 * 17], U1[9 * 17], U2[9 * 17];
    int t = threadIdx.x;
    int r = t / 17, c = t % 17;
    // Layer 1 (augmented 9 -> 17): T0 = Wr1^, T1 = Wl1^
    if (t < 9 * 17) {
        float wl, wr;
        if (r < 8) {
            wl = (c < 16) ? Wl1[r * 16 + c] : 0.f;
            wr = (c < 16) ? Wr1[r * 16 + c] : 0.f;
        } else {                 // constant row: bias enters via r-side, const passes through
            wl = 0.f;
            wr = (c < 16) ? b1[c] : 1.f;
        }
        T0[t] = wr;
        T1[t] = wl;
    }
    __syncthreads();
    // Layer 2 (17 -> 17)
    if (t < 9 * 17) {
        float a0 = 0.f, a1 = 0.f, a2 = 0.f;
        for (int k = 0; k < 17; k++) {
            float wr2 = (k < 16) ? ((c < 16) ? Wr2[k * 16 + c] : 0.f)
                                 : ((c < 16) ? b2[c] : 1.f);
            float wl2 = (k < 16 && c < 16) ? Wl2[k * 16 + c] : 0.f;
            float t0 = T0[r * 17 + k], t1 = T1[r * 17 + k];
            a0 += t0 * wr2;
            a1 += t1 * wr2 + t0 * wl2;
            a2 += t1 * wl2;
        }
        U0[t] = a0; U1[t] = a1; U2[t] = a2;
    }
    __syncthreads();
    // Layer 3 (17 -> 3), write C_k[9][3]
    if (t < 27) {
        int rr = t / 3, cc = t % 3;
        float c0 = 0.f, c1 = 0.f, c2 = 0.f, c3 = 0.f;
        for (int k = 0; k < 17; k++) {
            float wr3 = (k < 16) ? Wr3[k * 3 + cc] : b3[cc];
            float wl3 = (k < 16) ? Wl3[k * 3 + cc] : 0.f;
            float u0 = U0[rr * 17 + k], u1 = U1[rr * 17 + k], u2 = U2[rr * 17 + k];
            c0 += u0 * wr3;
            c1 += u1 * wr3 + u0 * wl3;
            c2 += u2 * wr3 + u1 * wl3;
            c3 += u2 * wl3;
        }
        Cmat[0 * 27 + t] = c0;
        Cmat[1 * 27 + t] = c1;
        Cmat[2 * 27 + t] = c2;
        Cmat[3 * 27 + t] = c3;
    }
}

// ---------------- K1: init features + zero scratch ----------------
__global__ void init_kernel(const float* __restrict__ x,
                            const float* __restrict__ w_pos,
                            const float* __restrict__ b_pos) {
    int i = blockIdx.x * blockDim.x + threadIdx.x;
    if (i >= Nn) return;
    float4 z4 = make_float4(0.f, 0.f, 0.f, 0.f);
    ((float4*)&S1v[i * 8])[0] = z4; ((float4*)&S1v[i * 8])[1] = z4;
    ((float4*)&S2v[i * 8])[0] = z4; ((float4*)&S2v[i * 8])[1] = z4;
    cntv[i] = 0; zcv[i] = 0;
    float fi = (float)i;
    float g[8];
    g[0] = x[i * 3 + 0]; g[1] = x[i * 3 + 1]; g[2] = x[i * 3 + 2];
#pragma unroll
    for (int p = 0; p < 5; p++) g[3 + p] = tanhf(fi * __ldg(&w_pos[p]) + __ldg(&b_pos[p]));
    ((float4*)&g0v[i * 8])[0] = *(float4*)&g[0];
    ((float4*)&g0v[i * 8])[1] = *(float4*)&g[4];
    if (i < NOUT) {
#pragma unroll
        for (int j = 0; j < 9; j++) out_acc[i * 9 + j] = 0.f;
    }
    if (i == 0) { c_count = 0; any_zero = 0; }
}

// ---------------- K2: pass A -- count degrees, scatter g0, compact dst<68 ----------------
__global__ void passA(const int* __restrict__ ei) {
    int t = blockIdx.x * blockDim.x + threadIdx.x;
    int base = t * 4;
    if (base >= Ee) return;
    int4 s4 = *(const int4*)&ei[base];
    int4 d4 = *(const int4*)&ei[Ee + base];
    int ss[4] = { s4.x, s4.y, s4.z, s4.w };
    int dd[4] = { d4.x, d4.y, d4.z, d4.w };
#pragma unroll
    for (int k = 0; k < 4; k++) {
        int s = ss[k], d = dd[k];
        atomicAdd(&cntv[d], 1);
        float4 a = __ldg((const float4*)&g0v[s * 8]);
        float4 b = __ldg((const float4*)&g0v[s * 8 + 4]);
        red_v4(&S1v[d * 8], a);
        red_v4(&S1v[d * 8 + 4], b);
        if (d < NOUT) {
            int p = atomicAdd(&c_count, 1);
            if (p < CAP) { c_src[p] = s; c_dst[p] = d; }
        }
    }
}

// ---------------- K3: normalize layer-1 sums -> g1 (in place) ----------------
__global__ void norm1() {
    int i = blockIdx.x * blockDim.x + threadIdx.x;
    if (i >= Nn) return;
    int c = cntv[i];
    if (c == 0) any_zero = 1;
    float inv = 1.f / (float)max(c, 1);
    float4* p = (float4*)&S1v[i * 8];
    float4 a = p[0], b = p[1];
    a.x *= inv; a.y *= inv; a.z *= inv; a.w *= inv;
    b.x *= inv; b.y *= inv; b.z *= inv; b.w *= inv;
    p[0] = a; p[1] = b;
}

// ---------------- K4: pass B -- scatter g1 ----------------
__global__ void passB(const int* __restrict__ ei) {
    int t = blockIdx.x * blockDim.x + threadIdx.x;
    int base = t * 4;
    if (base >= Ee) return;
    bool chk = (any_zero != 0);   // broadcast load; false in practice
    int4 s4 = *(const int4*)&ei[base];
    int4 d4 = *(const int4*)&ei[Ee + base];
    int ss[4] = { s4.x, s4.y, s4.z, s4.w };
    int dd[4] = { d4.x, d4.y, d4.z, d4.w };
#pragma unroll
    for (int k = 0; k < 4; k++) {
        int s = ss[k], d = dd[k];
        if (chk) {
            if (cntv[s] == 0) atomicAdd(&zcv[d], 1);
        }
        float4 a = __ldg((const float4*)&S1v[s * 8]);
        float4 b = __ldg((const float4*)&S1v[s * 8 + 4]);
        red_v4(&S2v[d * 8], a);
        red_v4(&S2v[d * 8 + 4], b);
    }
}

// ---------------- K5: normalize layer-2 sums -> g2; compute const column d2 ----------------
__global__ void norm2() {
    int i = blockIdx.x * blockDim.x + threadIdx.x;
    if (i >= Nn) return;
    int c = cntv[i];
    float inv = 1.f / (float)max(c, 1);
    float4* p = (float4*)&S2v[i * 8];
    float4 a = p[0], b = p[1];
    a.x *= inv; a.y *= inv; a.z *= inv; a.w *= inv;
    b.x *= inv; b.y *= inv; b.z *= inv; b.w *= inv;
    p[0] = a; p[1] = b;
    d2v[i] = (float)(c - zcv[i]) * inv;   // M(M(1))_i ; c==0 -> 0 correct
}

// ---------------- K6: pass C -- only the ~2k compacted edges with dst < 68 ----------------
__global__ void passC() {
    int i = blockIdx.x * blockDim.x + threadIdx.x;
    int cc = c_count; if (cc > CAP) cc = CAP;
    if (i >= cc) return;
    int s = c_src[i], d = c_dst[i];
#pragma unroll
    for (int j = 0; j < 8; j++) atomicAdd(&out_acc[d * 9 + j], S2v[s * 8 + j]);
    atomicAdd(&out_acc[d * 9 + 8], d2v[s]);
}

// ---------------- K7: final combine: out = sum_k G_k[:68] . C_k ----------------
__global__ void final_kernel(float* __restrict__ out) {
    int t = threadIdx.x;
    if (t >= NOUT * 3) return;
    int i = t / 3, c = t % 3;
    int cn = cntv[i];
    float inv = 1.f / (float)max(cn, 1);
    float acc = 0.f;
#pragma unroll
    for (int f = 0; f < 8; f++) acc += g0v[i * 8 + f] * Cmat[0 * 27 + f * 3 + c];
    acc += Cmat[0 * 27 + 8 * 3 + c];                        // G0 const col = 1
#pragma unroll
    for (int f = 0; f < 8; f++) acc += S1v[i * 8 + f] * Cmat[1 * 27 + f * 3 + c];
    acc += (cn > 0 ? 1.f : 0.f) * Cmat[1 * 27 + 8 * 3 + c]; // G1 const col = d1
#pragma unroll
    for (int f = 0; f < 8; f++) acc += S2v[i * 8 + f] * Cmat[2 * 27 + f * 3 + c];
    acc += d2v[i] * Cmat[2 * 27 + 8 * 3 + c];               // G2 const col = d2
#pragma unroll
    for (int f = 0; f < 9; f++) acc += out_acc[i * 9 + f] * inv * Cmat[3 * 27 + f * 3 + c];
    out[t] = acc;
}

// ---------------- launch ----------------
extern "C" void kernel_launch(void* const* d_in, const int* in_sizes, int n_in,
                              void* d_out, int out_size) {
    const float* x      = (const float*)d_in[0];
    const int*   ei     = (const int*)d_in[1];
    const float* w_pos  = (const float*)d_in[2];
    const float* b_pos  = (const float*)d_in[3];
    const float* Wl1    = (const float*)d_in[4];
    const float* Wr1    = (const float*)d_in[5];
    const float* b1     = (const float*)d_in[6];
    const float* Wl2    = (const float*)d_in[7];
    const float* Wr2    = (const float*)d_in[8];
    const float* b2     = (const float*)d_in[9];
    const float* Wl3    = (const float*)d_in[10];
    const float* Wr3    = (const float*)d_in[11];
    const float* b3     = (const float*)d_in[12];
    float* out = (float*)d_out;

    int nodeBlocks = (Nn + 255) / 256;
    int edgeBlocks = (Ee / 4 + 255) / 256;

    build_cmat<<<1, 160>>>(Wl1, Wr1, b1, Wl2, Wr2, b2, Wl3, Wr3, b3);
    init_kernel<<<nodeBlocks, 256>>>(x, w_pos, b_pos);
    passA<<<edgeBlocks, 256>>>(ei);
    norm1<<<nodeBlocks, 256>>>();
    passB<<<edgeBlocks, 256>>>(ei);
    norm2<<<nodeBlocks, 256>>>();
    passC<<<(CAP + 255) / 256, 256>>>();
    final_kernel<<<1, 256>>>(out);
}

// round 2
// speedup vs baseline: 1.0265x; 1.0265x over previous
#include <cuda_runtime.h>

#define Nn 150000
#define Ee 4800000
#define NOUT 68
#define NBLK_SCAN 147   // ceil(Nn / 1024)

// ---------------- device scratch (no allocation allowed) ----------------
__device__ __align__(16) float4 g0v[Nn * 2];   // augmented input features (8 dims as 2xfloat4)
__device__ __align__(16) float4 g1v[Nn * 2];   // layer-1 mean (normalized)
__device__ __align__(16) float4 g2v[Nn * 2];   // layer-2 mean (normalized)
__device__ int   cntv[Nn];        // in-degree
__device__ int   rowincl[Nn];     // per-block inclusive scan scratch
__device__ int   bsum[NBLK_SCAN];
__device__ int   boff[NBLK_SCAN];
__device__ int   rowstart[Nn + 1];
__device__ int   cursor[Nn];
__device__ int   csr[Ee];         // src node per edge, bucketed by dst
__device__ float d2v[Nn];         // const-column after 2 aggregations
__device__ int   any_zero;        // does any degree-0 node exist?
__device__ float out_acc[NOUT * 9];
__device__ float Cmat[4 * 27];    // C_k[9][3]

// ---------------- K0: build the 4 collapsed 9x3 weight matrices ----------------
__global__ void build_cmat(const float* __restrict__ Wl1, const float* __restrict__ Wr1,
                           const float* __restrict__ b1,
                           const float* __restrict__ Wl2, const float* __restrict__ Wr2,
                           const float* __restrict__ b2,
                           const float* __restrict__ Wl3, const float* __restrict__ Wr3,
                           const float* __restrict__ b3) {
    __shared__ float T0[9 * 17], T1[9 * 17];
    __shared__ float U0[9 * 17], U1[9 * 17], U2[9 * 17];
    int t = threadIdx.x;
    int r = t / 17, c = t % 17;
    if (t < 9 * 17) {
        float wl, wr;
        if (r < 8) {
            wl = (c < 16) ? Wl1[r * 16 + c] : 0.f;
            wr = (c < 16) ? Wr1[r * 16 + c] : 0.f;
        } else {
            wl = 0.f;
            wr = (c < 16) ? b1[c] : 1.f;
        }
        T0[t] = wr;
        T1[t] = wl;
    }
    __syncthreads();
    if (t < 9 * 17) {
        float a0 = 0.f, a1 = 0.f, a2 = 0.f;
        for (int k = 0; k < 17; k++) {
            float wr2 = (k < 16) ? ((c < 16) ? Wr2[k * 16 + c] : 0.f)
                                 : ((c < 16) ? b2[c] : 1.f);
            float wl2 = (k < 16 && c < 16) ? Wl2[k * 16 + c] : 0.f;
            float t0 = T0[r * 17 + k], t1 = T1[r * 17 + k];
            a0 += t0 * wr2;
            a1 += t1 * wr2 + t0 * wl2;
            a2 += t1 * wl2;
        }
        U0[t] = a0; U1[t] = a1; U2[t] = a2;
    }
    __syncthreads();
    if (t < 27) {
        int rr = t / 3, cc = t % 3;
        float c0 = 0.f, c1 = 0.f, c2 = 0.f, c3 = 0.f;
        for (int k = 0; k < 17; k++) {
            float wr3 = (k < 16) ? Wr3[k * 3 + cc] : b3[cc];
            float wl3 = (k < 16) ? Wl3[k * 3 + cc] : 0.f;
            float u0 = U0[rr * 17 + k], u1 = U1[rr * 17 + k], u2 = U2[rr * 17 + k];
            c0 += u0 * wr3;
            c1 += u1 * wr3 + u0 * wl3;
            c2 += u2 * wr3 + u1 * wl3;
            c3 += u2 * wl3;
        }
        Cmat[0 * 27 + t] = c0;
        Cmat[1 * 27 + t] = c1;
        Cmat[2 * 27 + t] = c2;
        Cmat[3 * 27 + t] = c3;
    }
}

// ---------------- K1: init features + zero degree ----------------
__global__ void init_kernel(const float* __restrict__ x,
                            const float* __restrict__ w_pos,
                            const float* __restrict__ b_pos) {
    int i = blockIdx.x * blockDim.x + threadIdx.x;
    if (i >= Nn) return;
    cntv[i] = 0;
    float fi = (float)i;
    float g[8];
    g[0] = x[i * 3 + 0]; g[1] = x[i * 3 + 1]; g[2] = x[i * 3 + 2];
#pragma unroll
    for (int p = 0; p < 5; p++) g[3 + p] = tanhf(fi * __ldg(&w_pos[p]) + __ldg(&b_pos[p]));
    g0v[i * 2 + 0] = *(float4*)&g[0];
    g0v[i * 2 + 1] = *(float4*)&g[4];
    if (i == 0) any_zero = 0;
}

// ---------------- K2: degree histogram (1 int atomic / edge) ----------------
__global__ void count_kernel(const int* __restrict__ ei) {
    int t = blockIdx.x * blockDim.x + threadIdx.x;
    int base = t * 4;
    if (base >= Ee) return;
    int4 d4 = __ldg((const int4*)&ei[Ee + base]);
    atomicAdd(&cntv[d4.x], 1);
    atomicAdd(&cntv[d4.y], 1);
    atomicAdd(&cntv[d4.z], 1);
    atomicAdd(&cntv[d4.w], 1);
}

// ---------------- K3a/b/c: prefix sum of degrees ----------------
__global__ void scanA() {
    __shared__ int sd[1024];
    int i = blockIdx.x * 1024 + threadIdx.x;
    int v = (i < Nn) ? cntv[i] : 0;
    if (i < Nn && v == 0) any_zero = 1;
    sd[threadIdx.x] = v;
    __syncthreads();
    for (int off = 1; off < 1024; off <<= 1) {
        int x = sd[threadIdx.x];
        if (threadIdx.x >= off) x += sd[threadIdx.x - off];
        __syncthreads();
        sd[threadIdx.x] = x;
        __syncthreads();
    }
    if (i < Nn) rowincl[i] = sd[threadIdx.x];
    if (threadIdx.x == 1023) bsum[blockIdx.x] = sd[1023];
}

__global__ void scanB() {
    int s = 0;
    for (int b = 0; b < NBLK_SCAN; b++) { boff[b] = s; s += bsum[b]; }
}

__global__ void scanC() {
    int i = blockIdx.x * blockDim.x + threadIdx.x;
    if (i >= Nn) return;
    int incl = rowincl[i] + boff[i >> 10];
    rowstart[i + 1] = incl;
    cursor[i] = incl - cntv[i];
    d2v[i] = (cntv[i] > 0) ? 1.f : 0.f;   // default; exact unless any_zero
    if (i == 0) rowstart[0] = 0;
}

// ---------------- K4: bucket fill (1 int atomic + 4B write / edge) ----------------
__global__ void fill_kernel(const int* __restrict__ ei) {
    int t = blockIdx.x * blockDim.x + threadIdx.x;
    int base = t * 4;
    if (base >= Ee) return;
    int4 s4 = __ldg((const int4*)&ei[base]);
    int4 d4 = __ldg((const int4*)&ei[Ee + base]);
    int ss[4] = { s4.x, s4.y, s4.z, s4.w };
    int dd[4] = { d4.x, d4.y, d4.z, d4.w };
#pragma unroll
    for (int k = 0; k < 4; k++) {
        int p = atomicAdd(&cursor[dd[k]], 1);
        csr[p] = ss[k];
    }
}

// ---------------- K5/K6: gather-aggregate, 2 lanes per node (float4 per lane) ----------
template <int PASS>
__global__ void gather8() {
    int t = blockIdx.x * blockDim.x + threadIdx.x;
    int node = t >> 1;
    int half = t & 1;
    if (node >= Nn) return;
    const float4* __restrict__ src = (PASS == 0) ? g0v : g1v;
    float4* __restrict__ dst = (PASS == 0) ? g1v : g2v;
    int beg = rowstart[node], end = rowstart[node + 1];
    float4 acc = make_float4(0.f, 0.f, 0.f, 0.f);
    int e = beg;
    for (; e + 2 <= end; e += 2) {
        int s0 = __ldg(&csr[e]);
        int s1 = __ldg(&csr[e + 1]);
        float4 a = __ldg(&src[s0 * 2 + half]);
        float4 b = __ldg(&src[s1 * 2 + half]);
        acc.x += a.x + b.x; acc.y += a.y + b.y;
        acc.z += a.z + b.z; acc.w += a.w + b.w;
    }
    if (e < end) {
        int s0 = __ldg(&csr[e]);
        float4 a = __ldg(&src[s0 * 2 + half]);
        acc.x += a.x; acc.y += a.y; acc.z += a.z; acc.w += a.w;
    }
    float inv = 1.f / (float)max(end - beg, 1);
    acc.x *= inv; acc.y *= inv; acc.z *= inv; acc.w *= inv;
    dst[node * 2 + half] = acc;
}

// ---------------- K7: exact d2 correction (cold path, ~never taken) ----------------
__global__ void d2fix() {
    if (any_zero == 0) return;
    int i = blockIdx.x * blockDim.x + threadIdx.x;
    if (i >= Nn) return;
    int beg = rowstart[i], end = rowstart[i + 1];
    int zc = 0;
    for (int e = beg; e < end; e++) zc += (cntv[csr[e]] == 0);
    d2v[i] = (float)(end - beg - zc) / (float)max(end - beg, 1);
}

// ---------------- K8: layer-3 aggregation for the 68 output rows ----------------
__global__ void layer3() {
    int w = (blockIdx.x * blockDim.x + threadIdx.x) >> 5;
    int lane = threadIdx.x & 31;
    if (w >= NOUT) return;
    int beg = rowstart[w], end = rowstart[w + 1];
    float acc[9];
#pragma unroll
    for (int j = 0; j < 9; j++) acc[j] = 0.f;
    for (int e = beg + lane; e < end; e += 32) {
        int s = csr[e];
        float4 a = g2v[s * 2], b = g2v[s * 2 + 1];
        acc[0] += a.x; acc[1] += a.y; acc[2] += a.z; acc[3] += a.w;
        acc[4] += b.x; acc[5] += b.y; acc[6] += b.z; acc[7] += b.w;
        acc[8] += d2v[s];
    }
#pragma unroll
    for (int off = 16; off; off >>= 1)
#pragma unroll
        for (int j = 0; j < 9; j++)
            acc[j] += __shfl_xor_sync(0xffffffffu, acc[j], off);
    if (lane == 0) {
        float inv = 1.f / (float)max(end - beg, 1);
#pragma unroll
        for (int j = 0; j < 9; j++) out_acc[w * 9 + j] = acc[j] * inv;
    }
}

// ---------------- K9: final combine: out = sum_k G_k[:68] . C_k ----------------
__global__ void final_kernel(float* __restrict__ out) {
    int t = threadIdx.x;
    if (t >= NOUT * 3) return;
    int i = t / 3, c = t % 3;
    const float* g0 = (const float*)g0v;
    const float* g1 = (const float*)g1v;
    const float* g2 = (const float*)g2v;
    int cn = cntv[i];
    float acc = 0.f;
#pragma unroll
    for (int f = 0; f < 8; f++) acc += g0[i * 8 + f] * Cmat[0 * 27 + f * 3 + c];
    acc += Cmat[0 * 27 + 8 * 3 + c];                        // G0 const col = 1
#pragma unroll
    for (int f = 0; f < 8; f++) acc += g1[i * 8 + f] * Cmat[1 * 27 + f * 3 + c];
    acc += (cn > 0 ? 1.f : 0.f) * Cmat[1 * 27 + 8 * 3 + c]; // G1 const col
#pragma unroll
    for (int f = 0; f < 8; f++) acc += g2[i * 8 + f] * Cmat[2 * 27 + f * 3 + c];
    acc += d2v[i] * Cmat[2 * 27 + 8 * 3 + c];               // G2 const col
#pragma unroll
    for (int f = 0; f < 9; f++) acc += out_acc[i * 9 + f] * Cmat[3 * 27 + f * 3 + c];
    out[t] = acc;
}

// ---------------- launch ----------------
extern "C" void kernel_launch(void* const* d_in, const int* in_sizes, int n_in,
                              void* d_out, int out_size) {
    const float* x      = (const float*)d_in[0];
    const int*   ei     = (const int*)d_in[1];
    const float* w_pos  = (const float*)d_in[2];
    const float* b_pos  = (const float*)d_in[3];
    const float* Wl1    = (const float*)d_in[4];
    const float* Wr1    = (const float*)d_in[5];
    const float* b1     = (const float*)d_in[6];
    const float* Wl2    = (const float*)d_in[7];
    const float* Wr2    = (const float*)d_in[8];
    const float* b2     = (const float*)d_in[9];
    const float* Wl3    = (const float*)d_in[10];
    const float* Wr3    = (const float*)d_in[11];
    const float* b3     = (const float*)d_in[12];
    float* out = (float*)d_out;

    int nodeBlocks  = (Nn + 255) / 256;
    int edgeBlocks  = (Ee / 4 + 255) / 256;
    int gathBlocks  = (Nn * 2 + 255) / 256;

    build_cmat<<<1, 160>>>(Wl1, Wr1, b1, Wl2, Wr2, b2, Wl3, Wr3, b3);
    init_kernel<<<nodeBlocks, 256>>>(x, w_pos, b_pos);
    count_kernel<<<edgeBlocks, 256>>>(ei);
    scanA<<<NBLK_SCAN, 1024>>>();
    scanB<<<1, 1>>>();
    scanC<<<nodeBlocks, 256>>>();
    fill_kernel<<<edgeBlocks, 256>>>(ei);
    gather8<0><<<gathBlocks, 256>>>();
    gather8<1><<<gathBlocks, 256>>>();
    d2fix<<<nodeBlocks, 256>>>();
    layer3<<<(NOUT * 32 + 127) / 128, 128>>>();
    final_kernel<<<1, 256>>>(out);
}

// round 4
// speedup vs baseline: 1.2113x; 1.1800x over previous
#include <cuda_runtime.h>

#define Nn 150000
#define Ee 4800000
#define NOUT 68
#define NBLK_SCAN 147   // ceil(Nn / 1024)
#define NW ((Nn + 31) / 32)

// ---------------- device scratch (no allocation allowed) ----------------
__device__ __align__(16) float4 g0v[Nn * 2];   // augmented input features (8 dims)
__device__ __align__(16) float4 g1v[Nn * 2];   // layer-1 mean
__device__ __align__(16) float4 g2v[Nn * 2];   // layer-2 mean
__device__ int   cntv[Nn];        // full in-degree (also exact zero-degree detector)
__device__ int   rowincl[Nn];
__device__ int   bsum[NBLK_SCAN];
__device__ int   boff[NBLK_SCAN];
__device__ int   rowstart[Nn + 1];
__device__ int   cursor[Nn];
__device__ int   csr[Ee];         // src per edge, bucketed by dst
__device__ float d2v[Nn];         // const-column after 2 aggregations
__device__ int   any_zero;
__device__ unsigned bit1[NW];     // S1 = in-neighbors of rows [0,68)
__device__ unsigned bit2[NW];     // S2 = in-neighbors of (S1 u [0,68))
__device__ float out_acc[NOUT * 9];
__device__ float Cmat[4 * 27];

// ---------------- K0: collapsed 9x3 weight matrices ----------------
__global__ void build_cmat(const float* __restrict__ Wl1, const float* __restrict__ Wr1,
                           const float* __restrict__ b1,
                           const float* __restrict__ Wl2, const float* __restrict__ Wr2,
                           const float* __restrict__ b2,
                           const float* __restrict__ Wl3, const float* __restrict__ Wr3,
                           const float* __restrict__ b3) {
    __shared__ float T0[9 * 17], T1[9 * 17];
    __shared__ float U0[9 * 17], U1[9 * 17], U2[9 * 17];
    int t = threadIdx.x;
    int r = t / 17, c = t % 17;
    if (t < 9 * 17) {
        float wl, wr;
        if (r < 8) {
            wl = (c < 16) ? Wl1[r * 16 + c] : 0.f;
            wr = (c < 16) ? Wr1[r * 16 + c] : 0.f;
        } else {
            wl = 0.f;
            wr = (c < 16) ? b1[c] : 1.f;
        }
        T0[t] = wr;
        T1[t] = wl;
    }
    __syncthreads();
    if (t < 9 * 17) {
        float a0 = 0.f, a1 = 0.f, a2 = 0.f;
        for (int k = 0; k < 17; k++) {
            float wr2 = (k < 16) ? ((c < 16) ? Wr2[k * 16 + c] : 0.f)
                                 : ((c < 16) ? b2[c] : 1.f);
            float wl2 = (k < 16 && c < 16) ? Wl2[k * 16 + c] : 0.f;
            float t0 = T0[r * 17 + k], t1 = T1[r * 17 + k];
            a0 += t0 * wr2;
            a1 += t1 * wr2 + t0 * wl2;
            a2 += t1 * wl2;
        }
        U0[t] = a0; U1[t] = a1; U2[t] = a2;
    }
    __syncthreads();
    if (t < 27) {
        int rr = t / 3, cc = t % 3;
        float c0 = 0.f, c1 = 0.f, c2 = 0.f, c3 = 0.f;
        for (int k = 0; k < 17; k++) {
            float wr3 = (k < 16) ? Wr3[k * 3 + cc] : b3[cc];
            float wl3 = (k < 16) ? Wl3[k * 3 + cc] : 0.f;
            float u0 = U0[rr * 17 + k], u1 = U1[rr * 17 + k], u2 = U2[rr * 17 + k];
            c0 += u0 * wr3;
            c1 += u1 * wr3 + u0 * wl3;
            c2 += u2 * wr3 + u1 * wl3;
            c3 += u2 * wl3;
        }
        Cmat[0 * 27 + t] = c0;
        Cmat[1 * 27 + t] = c1;
        Cmat[2 * 27 + t] = c2;
        Cmat[3 * 27 + t] = c3;
    }
}

// ---------------- K1: init ----------------
__global__ void init_kernel(const float* __restrict__ x,
                            const float* __restrict__ w_pos,
                            const float* __restrict__ b_pos) {
    int i = blockIdx.x * blockDim.x + threadIdx.x;
    if (i >= Nn) return;
    cntv[i] = 0;
    if (i < NW) { bit1[i] = 0u; bit2[i] = 0u; }
    float fi = (float)i;
    float g[8];
    g[0] = x[i * 3 + 0]; g[1] = x[i * 3 + 1]; g[2] = x[i * 3 + 2];
#pragma unroll
    for (int p = 0; p < 5; p++) g[3 + p] = tanhf(fi * __ldg(&w_pos[p]) + __ldg(&b_pos[p]));
    g0v[i * 2 + 0] = *(float4*)&g[0];
    g0v[i * 2 + 1] = *(float4*)&g[4];
    if (i == 0) any_zero = 0;
}

// ---------------- K2: full degree histogram ----------------
__global__ void count_kernel(const int* __restrict__ ei) {
    int t = blockIdx.x * blockDim.x + threadIdx.x;
    int base = t * 4;
    if (base >= Ee) return;
    int4 d4 = __ldg((const int4*)&ei[Ee + base]);
    atomicAdd(&cntv[d4.x], 1);
    atomicAdd(&cntv[d4.y], 1);
    atomicAdd(&cntv[d4.z], 1);
    atomicAdd(&cntv[d4.w], 1);
}

// ---------------- K3a/b/c: prefix sum of degrees ----------------
__global__ void scanA() {
    __shared__ int sd[1024];
    int i = blockIdx.x * 1024 + threadIdx.x;
    int v = (i < Nn) ? cntv[i] : 0;
    if (i < Nn && v == 0) any_zero = 1;
    sd[threadIdx.x] = v;
    __syncthreads();
    for (int off = 1; off < 1024; off <<= 1) {
        int x = sd[threadIdx.x];
        if (threadIdx.x >= off) x += sd[threadIdx.x - off];
        __syncthreads();
        sd[threadIdx.x] = x;
        __syncthreads();
    }
    if (i < Nn) rowincl[i] = sd[threadIdx.x];
    if (threadIdx.x == 1023) bsum[blockIdx.x] = sd[1023];
}

__global__ void scanB() {       // 1 block, 256 threads, Hillis-Steele over 147
    __shared__ int sd[256];
    int t = threadIdx.x;
    sd[t] = (t < NBLK_SCAN) ? bsum[t] : 0;
    __syncthreads();
    for (int off = 1; off < 256; off <<= 1) {
        int x = sd[t];
        if (t >= off) x += sd[t - off];
        __syncthreads();
        sd[t] = x;
        __syncthreads();
    }
    if (t < NBLK_SCAN) boff[t] = sd[t] - bsum[t];   // exclusive
}

__global__ void scanC() {
    int i = blockIdx.x * blockDim.x + threadIdx.x;
    if (i >= Nn) return;
    int incl = rowincl[i] + boff[i >> 10];
    rowstart[i + 1] = incl;
    cursor[i] = incl - cntv[i];
    d2v[i] = (cntv[i] > 0) ? 1.f : 0.f;   // exact unless any_zero (then d2fix)
    if (i == 0) rowstart[0] = 0;
}

// ---------------- K4: bucket fill ----------------
__global__ void fill_kernel(const int* __restrict__ ei) {
    int t = blockIdx.x * blockDim.x + threadIdx.x;
    int base = t * 4;
    if (base >= Ee) return;
    int4 s4 = __ldg((const int4*)&ei[base]);
    int4 d4 = __ldg((const int4*)&ei[Ee + base]);
    int ss[4] = { s4.x, s4.y, s4.z, s4.w };
    int dd[4] = { d4.x, d4.y, d4.z, d4.w };
#pragma unroll
    for (int k = 0; k < 4; k++) {
        int p = atomicAdd(&cursor[dd[k]], 1);
        csr[p] = ss[k];
    }
}

// ---------------- K4b: mark S1 (sources of edges into rows [0,68)) ----------------
__global__ void markS1() {
    int w = (blockIdx.x * blockDim.x + threadIdx.x) >> 5;   // 32 warps over 68 rows
    int lane = threadIdx.x & 31;
    for (int row = w; row < NOUT; row += 32) {
        int beg = rowstart[row], end = rowstart[row + 1];
        for (int e = beg + lane; e < end; e += 32) {
            int s = csr[e];
            atomicOr(&bit1[s >> 5], 1u << (s & 31));
        }
    }
}

// ---------------- K4c: mark S2 (sources of edges into S1 u [0,68)) ----------------
__global__ void markS2() {
    int i = blockIdx.x * blockDim.x + threadIdx.x;
    if (i >= Nn) return;
    bool in = ((bit1[i >> 5] >> (i & 31)) & 1u) || (i < NOUT);
    if (!in) return;
    int beg = rowstart[i], end = rowstart[i + 1];
    for (int e = beg; e < end; e++) {
        int s = csr[e];
        atomicOr(&bit2[s >> 5], 1u << (s & 31));
    }
}

// ---------------- K5/K6: predicated gather-aggregate, 2 lanes per node ----------
template <int PASS>
__global__ void gather8() {
    int t = blockIdx.x * blockDim.x + threadIdx.x;
    int node = t >> 1;
    int half = t & 1;
    if (node >= Nn) return;
    const unsigned* __restrict__ msk = (PASS == 0) ? bit2 : bit1;
    bool need = ((msk[node >> 5] >> (node & 31)) & 1u) || (node < NOUT);
    if (!need) return;
    const float4* __restrict__ src = (PASS == 0) ? g0v : g1v;
    float4* __restrict__ dst = (PASS == 0) ? g1v : g2v;
    int beg = rowstart[node], end = rowstart[node + 1];
    float4 acc = make_float4(0.f, 0.f, 0.f, 0.f);
    int e = beg;
    for (; e + 2 <= end; e += 2) {
        int s0 = __ldg(&csr[e]);
        int s1 = __ldg(&csr[e + 1]);
        float4 a = __ldg(&src[s0 * 2 + half]);
        float4 b = __ldg(&src[s1 * 2 + half]);
        acc.x += a.x + b.x; acc.y += a.y + b.y;
        acc.z += a.z + b.z; acc.w += a.w + b.w;
    }
    if (e < end) {
        int s0 = __ldg(&csr[e]);
        float4 a = __ldg(&src[s0 * 2 + half]);
        acc.x += a.x; acc.y += a.y; acc.z += a.z; acc.w += a.w;
    }
    float inv = 1.f / (float)max(end - beg, 1);
    acc.x *= inv; acc.y *= inv; acc.z *= inv; acc.w *= inv;
    dst[node * 2 + half] = acc;
}

// ---------------- K7: exact d2 correction (cold path) ----------------
__global__ void d2fix() {
    if (any_zero == 0) return;
    int i = blockIdx.x * blockDim.x + threadIdx.x;
    if (i >= Nn) return;
    int beg = rowstart[i], end = rowstart[i + 1];
    int zc = 0;
    for (int e = beg; e < end; e++) zc += (cntv[csr[e]] == 0);
    d2v[i] = (float)(end - beg - zc) / (float)max(end - beg, 1);
}

// ---------------- K8: layer-3 aggregation for the 68 output rows ----------------
__global__ void layer3() {
    int w = (blockIdx.x * blockDim.x + threadIdx.x) >> 5;
    int lane = threadIdx.x & 31;
    if (w >= NOUT) return;
    int beg = rowstart[w], end = rowstart[w + 1];
    float acc[9];
#pragma unroll
    for (int j = 0; j < 9; j++) acc[j] = 0.f;
    for (int e = beg + lane; e < end; e += 32) {
        int s = csr[e];
        float4 a = g2v[s * 2], b = g2v[s * 2 + 1];
        acc[0] += a.x; acc[1] += a.y; acc[2] += a.z; acc[3] += a.w;
        acc[4] += b.x; acc[5] += b.y; acc[6] += b.z; acc[7] += b.w;
        acc[8] += d2v[s];
    }
#pragma unroll
    for (int off = 16; off; off >>= 1)
#pragma unroll
        for (int j = 0; j < 9; j++)
            acc[j] += __shfl_xor_sync(0xffffffffu, acc[j], off);
    if (lane == 0) {
        float inv = 1.f / (float)max(end - beg, 1);
#pragma unroll
        for (int j = 0; j < 9; j++) out_acc[w * 9 + j] = acc[j] * inv;
    }
}

// ---------------- K9: final combine ----------------
__global__ void final_kernel(float* __restrict__ out) {
    int t = threadIdx.x;
    if (t >= NOUT * 3) return;
    int i = t / 3, c = t % 3;
    const float* g0 = (const float*)g0v;
    const float* g1 = (const float*)g1v;
    const float* g2 = (const float*)g2v;
    int cn = cntv[i];
    float acc = 0.f;
#pragma unroll
    for (int f = 0; f < 8; f++) acc += g0[i * 8 + f] * Cmat[0 * 27 + f * 3 + c];
    acc += Cmat[0 * 27 + 8 * 3 + c];
#pragma unroll
    for (int f = 0; f < 8; f++) acc += g1[i * 8 + f] * Cmat[1 * 27 + f * 3 + c];
    acc += (cn > 0 ? 1.f : 0.f) * Cmat[1 * 27 + 8 * 3 + c];
#pragma unroll
    for (int f = 0; f < 8; f++) acc += g2[i * 8 + f] * Cmat[2 * 27 + f * 3 + c];
    acc += d2v[i] * Cmat[2 * 27 + 8 * 3 + c];
#pragma unroll
    for (int f = 0; f < 9; f++) acc += out_acc[i * 9 + f] * Cmat[3 * 27 + f * 3 + c];
    out[t] = acc;
}

// ---------------- launch ----------------
extern "C" void kernel_launch(void* const* d_in, const int* in_sizes, int n_in,
                              void* d_out, int out_size) {
    const float* x      = (const float*)d_in[0];
    const int*   ei     = (const int*)d_in[1];
    const float* w_pos  = (const float*)d_in[2];
    const float* b_pos  = (const float*)d_in[3];
    const float* Wl1    = (const float*)d_in[4];
    const float* Wr1    = (const float*)d_in[5];
    const float* b1     = (const float*)d_in[6];
    const float* Wl2    = (const float*)d_in[7];
    const float* Wr2    = (const float*)d_in[8];
    const float* b2     = (const float*)d_in[9];
    const float* Wl3    = (const float*)d_in[10];
    const float* Wr3    = (const float*)d_in[11];
    const float* b3     = (const float*)d_in[12];
    float* out = (float*)d_out;

    int nodeBlocks  = (Nn + 255) / 256;
    int edgeBlocks  = (Ee / 4 + 255) / 256;
    int gathBlocks  = (Nn * 2 + 255) / 256;

    build_cmat<<<1, 160>>>(Wl1, Wr1, b1, Wl2, Wr2, b2, Wl3, Wr3, b3);
    init_kernel<<<nodeBlocks, 256>>>(x, w_pos, b_pos);
    count_kernel<<<edgeBlocks, 256>>>(ei);
    scanA<<<NBLK_SCAN, 1024>>>();
    scanB<<<1, 256>>>();
    scanC<<<nodeBlocks, 256>>>();
    fill_kernel<<<edgeBlocks, 256>>>(ei);
    markS1<<<4, 256>>>();
    markS2<<<nodeBlocks, 256>>>();
    gather8<0><<<gathBlocks, 256>>>();
    gather8<1><<<gathBlocks, 256>>>();
    d2fix<<<nodeBlocks, 256>>>();
    layer3<<<(NOUT * 32 + 127) / 128, 128>>>();
    final_kernel<<<1, 256>>>(out);
}

// round 6
// speedup vs baseline: 1.4772x; 1.2195x over previous
#include <cuda_runtime.h>

#define Nn 150000
#define Ee 4800000
#define NOUT 68
#define NW ((Nn + 31) / 32)
#define CAP68 8192
#define CAP2 131072

// ---------------- device scratch (no allocation allowed) ----------------
__device__ __align__(16) float4 g0v[Nn * 2];   // augmented input features (8 dims)
__device__ __align__(16) float4 g1v[Nn * 2];   // S1sum -> layer-1 mean (masked nodes)
__device__ __align__(16) float4 g2v[Nn * 2];   // S2sum -> layer-2 mean (masked nodes)
__device__ int   cntv[Nn];        // in-degree (exact at masked nodes)
__device__ int   zcv[Nn];         // cold-path: # zero-degree in-neighbors
__device__ float d2v[Nn];         // const-column after 2 aggregations
__device__ int   any_zero;
__device__ unsigned bit1[NW];     // S1 = in-neighbors of rows [0,68)
__device__ unsigned bit2[NW];     // S2 = in-neighbors of (S1 u [0,68))
__device__ int2  l68[CAP68];      // edges with dst < 68
__device__ int   n68;
__device__ int2  l2v[CAP2];       // edges with dst in S1 u [0,68)
__device__ int   n2;
__device__ float out_acc[NOUT * 9];
__device__ float Cmat[4 * 27];

__device__ __forceinline__ bool tb1(int v) {
    return (v < NOUT) || ((__ldg(&bit1[v >> 5]) >> (v & 31)) & 1u);
}
__device__ __forceinline__ bool tb2(int v) {
    return (__ldg(&bit2[v >> 5]) >> (v & 31)) & 1u;
}
__device__ __forceinline__ void red_v4(float* addr, float4 v) {
    asm volatile("red.global.add.v4.f32 [%0], {%1,%2,%3,%4};"
                 :: "l"(addr), "f"(v.x), "f"(v.y), "f"(v.z), "f"(v.w)
                 : "memory");
}

// ---------------- K0: collapsed 9x3 weight matrices ----------------
__global__ void build_cmat(const float* __restrict__ Wl1, const float* __restrict__ Wr1,
                           const float* __restrict__ b1,
                           const float* __restrict__ Wl2, const float* __restrict__ Wr2,
                           const float* __restrict__ b2,
                           const float* __restrict__ Wl3, const float* __restrict__ Wr3,
                           const float* __restrict__ b3) {
    __shared__ float T0[9 * 17], T1[9 * 17];
    __shared__ float U0[9 * 17], U1[9 * 17], U2[9 * 17];
    int t = threadIdx.x;
    int r = t / 17, c = t % 17;
    if (t < 9 * 17) {
        float wl, wr;
        if (r < 8) {
            wl = (c < 16) ? Wl1[r * 16 + c] : 0.f;
            wr = (c < 16) ? Wr1[r * 16 + c] : 0.f;
        } else {
            wl = 0.f;
            wr = (c < 16) ? b1[c] : 1.f;
        }
        T0[t] = wr;
        T1[t] = wl;
    }
    __syncthreads();
    if (t < 9 * 17) {
        float a0 = 0.f, a1 = 0.f, a2 = 0.f;
        for (int k = 0; k < 17; k++) {
            float wr2 = (k < 16) ? ((c < 16) ? Wr2[k * 16 + c] : 0.f)
                                 : ((c < 16) ? b2[c] : 1.f);
            float wl2 = (k < 16 && c < 16) ? Wl2[k * 16 + c] : 0.f;
            float t0 = T0[r * 17 + k], t1 = T1[r * 17 + k];
            a0 += t0 * wr2;
            a1 += t1 * wr2 + t0 * wl2;
            a2 += t1 * wl2;
        }
        U0[t] = a0; U1[t] = a1; U2[t] = a2;
    }
    __syncthreads();
    if (t < 27) {
        int rr = t / 3, cc = t % 3;
        float c0 = 0.f, c1 = 0.f, c2 = 0.f, c3 = 0.f;
        for (int k = 0; k < 17; k++) {
            float wr3 = (k < 16) ? Wr3[k * 3 + cc] : b3[cc];
            float wl3 = (k < 16) ? Wl3[k * 3 + cc] : 0.f;
            float u0 = U0[rr * 17 + k], u1 = U1[rr * 17 + k], u2 = U2[rr * 17 + k];
            c0 += u0 * wr3;
            c1 += u1 * wr3 + u0 * wl3;
            c2 += u2 * wr3 + u1 * wl3;
            c3 += u2 * wl3;
        }
        Cmat[0 * 27 + t] = c0;
        Cmat[1 * 27 + t] = c1;
        Cmat[2 * 27 + t] = c2;
        Cmat[3 * 27 + t] = c3;
    }
}

// ---------------- K1: init everything + compute g0 ----------------
__global__ void init_kernel(const float* __restrict__ x,
                            const float* __restrict__ w_pos,
                            const float* __restrict__ b_pos) {
    int i = blockIdx.x * blockDim.x + threadIdx.x;
    if (i >= Nn) return;
    cntv[i] = 0; zcv[i] = 0;
    float4 z = make_float4(0.f, 0.f, 0.f, 0.f);
    g1v[i * 2] = z; g1v[i * 2 + 1] = z;
    g2v[i * 2] = z; g2v[i * 2 + 1] = z;
    if (i < NW) { bit1[i] = 0u; bit2[i] = 0u; }
    if (i < NOUT) {
#pragma unroll
        for (int j = 0; j < 9; j++) out_acc[i * 9 + j] = 0.f;
    }
    if (i == 0) { n68 = 0; n2 = 0; any_zero = 0; }
    float fi = (float)i;
    float g[8];
    g[0] = x[i * 3 + 0]; g[1] = x[i * 3 + 1]; g[2] = x[i * 3 + 2];
#pragma unroll
    for (int p = 0; p < 5; p++) g[3 + p] = tanhf(fi * __ldg(&w_pos[p]) + __ldg(&b_pos[p]));
    g0v[i * 2 + 0] = *(float4*)&g[0];
    g0v[i * 2 + 1] = *(float4*)&g[4];
}

// ---------------- K2: scan1 -- mark S1, compact dst<68 edges ----------------
__global__ void scan1(const int* __restrict__ ei) {
    int t = blockIdx.x * blockDim.x + threadIdx.x;
    int base = t * 4;
    if (base >= Ee) return;
    int4 d4 = __ldg((const int4*)&ei[Ee + base]);
    int dd[4] = { d4.x, d4.y, d4.z, d4.w };
    bool anyhit = (dd[0] < NOUT) | (dd[1] < NOUT) | (dd[2] < NOUT) | (dd[3] < NOUT);
    if (!anyhit) return;
    int4 s4 = __ldg((const int4*)&ei[base]);
    int ss[4] = { s4.x, s4.y, s4.z, s4.w };
#pragma unroll
    for (int k = 0; k < 4; k++) {
        if (dd[k] < NOUT) {
            int s = ss[k];
            unsigned m = 1u << (s & 31);
            if (!(__ldg(&bit1[s >> 5]) & m)) atomicOr(&bit1[s >> 5], m);
            int p = atomicAdd(&n68, 1);
            if (p < CAP68) l68[p] = make_int2(s, dd[k]);
        }
    }
}

// ---------------- K3: scan2 -- mark S2, compact dst in S1uO edges ----------------
__global__ void scan2(const int* __restrict__ ei) {
    int t = blockIdx.x * blockDim.x + threadIdx.x;
    int base = t * 4;
    if (base >= Ee) return;
    int4 d4 = __ldg((const int4*)&ei[Ee + base]);
    int dd[4] = { d4.x, d4.y, d4.z, d4.w };
    bool h0 = tb1(dd[0]), h1 = tb1(dd[1]), h2 = tb1(dd[2]), h3 = tb1(dd[3]);
    if (!(h0 | h1 | h2 | h3)) return;
    int4 s4 = __ldg((const int4*)&ei[base]);
    int ss[4] = { s4.x, s4.y, s4.z, s4.w };
    bool hh[4] = { h0, h1, h2, h3 };
#pragma unroll
    for (int k = 0; k < 4; k++) {
        if (hh[k]) {
            int s = ss[k];
            unsigned m = 1u << (s & 31);
            if (!(__ldg(&bit2[s >> 5]) & m)) atomicOr(&bit2[s >> 5], m);
            int p = atomicAdd(&n2, 1);
            if (p < CAP2) l2v[p] = make_int2(s, dd[k]);
        }
    }
}

// ---------------- K4: scan3 -- masked count + masked g0 scatter (fused) ----------
__global__ void scan3(const int* __restrict__ ei) {
    int t = blockIdx.x * blockDim.x + threadIdx.x;
    int base = t * 4;
    if (base >= Ee) return;
    int4 d4 = __ldg((const int4*)&ei[Ee + base]);
    int dd[4] = { d4.x, d4.y, d4.z, d4.w };
    bool f0 = tb2(dd[0]) | (dd[0] < NOUT);
    bool f1 = tb2(dd[1]) | (dd[1] < NOUT);
    bool f2 = tb2(dd[2]) | (dd[2] < NOUT);
    bool f3 = tb2(dd[3]) | (dd[3] < NOUT);
    bool c0 = f0 | tb1(dd[0]);
    bool c1 = f1 | tb1(dd[1]);
    bool c2 = f2 | tb1(dd[2]);
    bool c3 = f3 | tb1(dd[3]);
    if (!(c0 | c1 | c2 | c3)) return;
    int4 s4 = __ldg((const int4*)&ei[base]);
    int ss[4] = { s4.x, s4.y, s4.z, s4.w };
    bool ff[4] = { f0, f1, f2, f3 };
    bool cc[4] = { c0, c1, c2, c3 };
#pragma unroll
    for (int k = 0; k < 4; k++) {
        if (cc[k]) atomicAdd(&cntv[dd[k]], 1);
        if (ff[k]) {
            int s = ss[k], d = dd[k];
            float4 a = __ldg(&g0v[s * 2]);
            float4 b = __ldg(&g0v[s * 2 + 1]);
            red_v4((float*)&g1v[d * 2], a);
            red_v4((float*)&g1v[d * 2 + 1], b);
        }
    }
}

// ---------------- K5: norm1 -- g1 = S1sum/cnt at bit2|O; d2 default; any_zero --
__global__ void norm1() {
    int i = blockIdx.x * blockDim.x + threadIdx.x;
    if (i >= Nn) return;
    bool b2m = tb2(i);
    bool need1 = b2m || (i < NOUT);
    int c = cntv[i];
    if (need1) {
        if (b2m && c == 0) any_zero = 1;
        float inv = 1.f / (float)max(c, 1);
        float4 a = g1v[i * 2], b = g1v[i * 2 + 1];
        a.x *= inv; a.y *= inv; a.z *= inv; a.w *= inv;
        b.x *= inv; b.y *= inv; b.z *= inv; b.w *= inv;
        g1v[i * 2] = a; g1v[i * 2 + 1] = b;
    }
    if (tb1(i)) d2v[i] = (c > 0) ? 1.f : 0.f;
}

// ---------------- K6: passB -- scatter g1 over compacted list2 (~70K edges) ----
__global__ void passB() {
    int i = blockIdx.x * blockDim.x + threadIdx.x;
    if (i >= n2 || i >= CAP2) return;
    int2 e = l2v[i];
    float4 a = __ldg(&g1v[e.x * 2]);
    float4 b = __ldg(&g1v[e.x * 2 + 1]);
    red_v4((float*)&g2v[e.y * 2], a);
    red_v4((float*)&g2v[e.y * 2 + 1], b);
}

// ---------------- K7: norm2 -- g2 = S2sum/cnt at bit1|O ----------------
__global__ void norm2() {
    int i = blockIdx.x * blockDim.x + threadIdx.x;
    if (i >= Nn) return;
    if (!tb1(i)) return;
    float inv = 1.f / (float)max(cntv[i], 1);
    float4 a = g2v[i * 2], b = g2v[i * 2 + 1];
    a.x *= inv; a.y *= inv; a.z *= inv; a.w *= inv;
    b.x *= inv; b.y *= inv; b.z *= inv; b.w *= inv;
    g2v[i * 2] = a; g2v[i * 2 + 1] = b;
}

// ---------------- K8a/K8b: exact d2 correction (cold path) ----------------
__global__ void d2fixA() {
    if (any_zero == 0) return;
    int i = blockIdx.x * blockDim.x + threadIdx.x;
    if (i >= n2 || i >= CAP2) return;
    int2 e = l2v[i];
    if (cntv[e.x] == 0) atomicAdd(&zcv[e.y], 1);
}
__global__ void d2fixB() {
    if (any_zero == 0) return;
    int i = blockIdx.x * blockDim.x + threadIdx.x;
    if (i >= Nn) return;
    if (!tb1(i)) return;
    int c = cntv[i];
    d2v[i] = (float)(c - zcv[i]) / (float)max(c, 1);
}

// ---------------- K9: passC -- layer-3 scatter over list68 (~2K edges) --------
__global__ void passC() {
    int i = blockIdx.x * blockDim.x + threadIdx.x;
    if (i >= n68 || i >= CAP68) return;
    int2 e = l68[i];
    int s = e.x, d = e.y;
    float4 a = g2v[s * 2], b = g2v[s * 2 + 1];
    atomicAdd(&out_acc[d * 9 + 0], a.x);
    atomicAdd(&out_acc[d * 9 + 1], a.y);
    atomicAdd(&out_acc[d * 9 + 2], a.z);
    atomicAdd(&out_acc[d * 9 + 3], a.w);
    atomicAdd(&out_acc[d * 9 + 4], b.x);
    atomicAdd(&out_acc[d * 9 + 5], b.y);
    atomicAdd(&out_acc[d * 9 + 6], b.z);
    atomicAdd(&out_acc[d * 9 + 7], b.w);
    atomicAdd(&out_acc[d * 9 + 8], d2v[s]);
}

// ---------------- K10: final combine ----------------
__global__ void final_kernel(float* __restrict__ out) {
    int t = threadIdx.x;
    if (t >= NOUT * 3) return;
    int i = t / 3, c = t % 3;
    const float* g0 = (const float*)g0v;
    const float* g1 = (const float*)g1v;
    const float* g2 = (const float*)g2v;
    int cn = cntv[i];
    float inv = 1.f / (float)max(cn, 1);
    float acc = 0.f;
#pragma unroll
    for (int f = 0; f < 8; f++) acc += g0[i * 8 + f] * Cmat[0 * 27 + f * 3 + c];
    acc += Cmat[0 * 27 + 8 * 3 + c];
#pragma unroll
    for (int f = 0; f < 8; f++) acc += g1[i * 8 + f] * Cmat[1 * 27 + f * 3 + c];
    acc += (cn > 0 ? 1.f : 0.f) * Cmat[1 * 27 + 8 * 3 + c];
#pragma unroll
    for (int f = 0; f < 8; f++) acc += g2[i * 8 + f] * Cmat[2 * 27 + f * 3 + c];
    acc += d2v[i] * Cmat[2 * 27 + 8 * 3 + c];
#pragma unroll
    for (int f = 0; f < 9; f++) acc += out_acc[i * 9 + f] * inv * Cmat[3 * 27 + f * 3 + c];
    out[t] = acc;
}

// ---------------- launch ----------------
extern "C" void kernel_launch(void* const* d_in, const int* in_sizes, int n_in,
                              void* d_out, int out_size) {
    const float* x      = (const float*)d_in[0];
    const int*   ei     = (const int*)d_in[1];
    const float* w_pos  = (const float*)d_in[2];
    const float* b_pos  = (const float*)d_in[3];
    const float* Wl1    = (const float*)d_in[4];
    const float* Wr1    = (const float*)d_in[5];
    const float* b1     = (const float*)d_in[6];
    const float* Wl2    = (const float*)d_in[7];
    const float* Wr2    = (const float*)d_in[8];
    const float* b2     = (const float*)d_in[9];
    const float* Wl3    = (const float*)d_in[10];
    const float* Wr3    = (const float*)d_in[11];
    const float* b3     = (const float*)d_in[12];
    float* out = (float*)d_out;

    int nodeBlocks = (Nn + 255) / 256;
    int edgeBlocks = (Ee / 4 + 255) / 256;

    build_cmat<<<1, 160>>>(Wl1, Wr1, b1, Wl2, Wr2, b2, Wl3, Wr3, b3);
    init_kernel<<<nodeBlocks, 256>>>(x, w_pos, b_pos);
    scan1<<<edgeBlocks, 256>>>(ei);
    scan2<<<edgeBlocks, 256>>>(ei);
    scan3<<<edgeBlocks, 256>>>(ei);
    norm1<<<nodeBlocks, 256>>>();
    passB<<<CAP2 / 256, 256>>>();
    norm2<<<nodeBlocks, 256>>>();
    d2fixA<<<CAP2 / 256, 256>>>();
    d2fixB<<<nodeBlocks, 256>>>();
    passC<<<CAP68 / 256, 256>>>();
    final_kernel<<<1, 256>>>(out);
}